// round 3
// baseline (speedup 1.0000x reference)
#include <cuda_runtime.h>

// Problem constants
#define DLEG   32
#define BATCH  256
#define NCOLS  1024                 // D*D
#define KDIM   1024                 // D*D
#define NODE_SZ (DLEG*DLEG*DLEG*DLEG)   // 1048576 floats per node
#define XSZ    (BATCH*DLEG*DLEG*DLEG)   // 8388608 floats per state

// Ping-pong scratch (allocation-free workaround: __device__ globals)
__device__ float g_buf0[XSZ];
__device__ float g_buf1[XSZ];

// GEMM tiling
#define BM 128
#define BN 128
#define BK 16
#define NT (KDIM / BK)   // 64 k-tiles

// MODE 0: step 0.  A[row=(b,f), k=(i,j)] = X[b,i,j,f] ; W row = k (natural)
// MODE 1: steps 1-5. reduction re-indexed k'=(j,i):
//         A[row=(b,f), k'] = X[b,j,f,i] (i contiguous) ; W row = i*32 + j
template <int MODE, bool EPI>
__global__ __launch_bounds__(256, 2)
void entangler_gemm(const float* __restrict__ Xext,
                    const float* __restrict__ Wn,
                    const float* __restrict__ bias,
                    float* __restrict__ Oext,
                    int src_sel, int dst_sel)
{
    const float* __restrict__ X =
        (src_sel == 0) ? Xext : (src_sel == 1 ? (const float*)g_buf0 : (const float*)g_buf1);
    float* __restrict__ O =
        (dst_sel == 0) ? Oext : (dst_sel == 1 ? g_buf0 : g_buf1);

    __shared__ __align__(16) float As[2][BK][BM];
    __shared__ __align__(16) float Bs[2][BK][BN];

    const int tid  = threadIdx.x;
    const int col0 = blockIdx.x * BN;   // 0..7  * 128
    const int row0 = blockIdx.y * BM;   // 0..63 * 128

    // compute-thread mapping: 16x16 threads, split 4+4 fragments
    const int tcol = tid & 15;
    const int trow = tid >> 4;

    // ---- A load mapping ----
    // MODE 0: per thread: kk = tid>>4 (0..15), row group rg = tid&15 -> rows rg*8..+7 (f contiguous)
    const int a_kk = tid >> 4;
    const int a_rg = tid & 15;
    const int m0_base = row0 + a_rg * 8;      // stays within one b (8 | 32)
    const int m0_b    = m0_base >> 5;
    const int m0_f    = m0_base & 31;
    // MODE 1: per thread: row r = tid>>1 (0..127), half h = tid&1 -> 8 contiguous k' (i) values
    const int a_r  = tid >> 1;
    const int a_h  = tid & 1;
    const int m1_row = row0 + a_r;
    const int m1_b   = m1_row >> 5;
    const int m1_f   = m1_row & 31;

    // ---- B load mapping: kk = tid>>4, 8 contiguous cols ----
    const int b_kk = tid >> 4;
    const int b_c  = (tid & 15) * 8;

    float4 arv0, arv1, brv0, brv1;

    auto load_gmem = [&](int kt) {
        if (MODE == 0) {
            // i = kt>>1, j = (kt&1)*16 + a_kk ; 8 contiguous f
            const float* p = X + m0_b * 32768 + (kt >> 1) * 1024
                               + (((kt & 1) << 4) + a_kk) * 32 + m0_f;
            arv0 = *(const float4*)(p);
            arv1 = *(const float4*)(p + 4);
        } else {
            // j = kt>>1 ; i = (kt&1)*16 + a_h*8 + u, contiguous
            const float* p = X + m1_b * 32768 + (kt >> 1) * 1024
                               + m1_f * 32 + ((kt & 1) << 4) + a_h * 8;
            arv0 = *(const float4*)(p);
            arv1 = *(const float4*)(p + 4);
        }
        int wrow;
        if (MODE == 0) wrow = kt * 16 + b_kk;
        else {
            int wi = ((kt & 1) << 4) + b_kk;   // i
            int wj = kt >> 1;                  // j
            wrow = wi * 32 + wj;
        }
        const float* q = Wn + wrow * 1024 + col0 + b_c;
        brv0 = *(const float4*)(q);
        brv1 = *(const float4*)(q + 4);
    };

    auto store_smem = [&](int buf) {
        if (MODE == 0) {
            *(float4*)&As[buf][a_kk][a_rg * 8]     = arv0;
            *(float4*)&As[buf][a_kk][a_rg * 8 + 4] = arv1;
        } else {
            As[buf][a_h * 8 + 0][a_r] = arv0.x;
            As[buf][a_h * 8 + 1][a_r] = arv0.y;
            As[buf][a_h * 8 + 2][a_r] = arv0.z;
            As[buf][a_h * 8 + 3][a_r] = arv0.w;
            As[buf][a_h * 8 + 4][a_r] = arv1.x;
            As[buf][a_h * 8 + 5][a_r] = arv1.y;
            As[buf][a_h * 8 + 6][a_r] = arv1.z;
            As[buf][a_h * 8 + 7][a_r] = arv1.w;
        }
        *(float4*)&Bs[buf][b_kk][b_c]     = brv0;
        *(float4*)&Bs[buf][b_kk][b_c + 4] = brv1;
    };

    float acc[8][8];
#pragma unroll
    for (int r = 0; r < 8; r++)
#pragma unroll
        for (int c = 0; c < 8; c++) acc[r][c] = 0.0f;

    auto compute = [&](int cur) {
#pragma unroll
        for (int kk = 0; kk < BK; kk++) {
            float4 a0 = *(const float4*)&As[cur][kk][trow * 4];
            float4 a1 = *(const float4*)&As[cur][kk][64 + trow * 4];
            float4 b0 = *(const float4*)&Bs[cur][kk][tcol * 4];
            float4 b1 = *(const float4*)&Bs[cur][kk][64 + tcol * 4];
            float af[8] = {a0.x, a0.y, a0.z, a0.w, a1.x, a1.y, a1.z, a1.w};
            float bf[8] = {b0.x, b0.y, b0.z, b0.w, b1.x, b1.y, b1.z, b1.w};
#pragma unroll
            for (int r = 0; r < 8; r++)
#pragma unroll
                for (int c = 0; c < 8; c++)
                    acc[r][c] = fmaf(af[r], bf[c], acc[r][c]);
        }
    };

    load_gmem(0);
    store_smem(0);
    __syncthreads();

#pragma unroll 1
    for (int kt = 0; kt < NT; kt++) {
        const int cur = kt & 1;
        if (kt + 1 < NT) load_gmem(kt + 1);
        compute(cur);
        if (kt + 1 < NT) {
            store_smem(cur ^ 1);
            __syncthreads();
        }
    }

    // Epilogue: output is contiguous (B, free, m, n) = O[row*1024 + col]
#pragma unroll
    for (int u = 0; u < 8; u++) {
        const int r    = (u < 4) ? (trow * 4 + u) : (64 + trow * 4 + (u - 4));
        const int grow = row0 + r;
#pragma unroll
        for (int h = 0; h < 2; h++) {
            const int c    = (h == 0) ? (tcol * 4) : (64 + tcol * 4);
            const int gcol = col0 + c;
            float4 v = make_float4(acc[u][h * 4 + 0], acc[u][h * 4 + 1],
                                   acc[u][h * 4 + 2], acc[u][h * 4 + 3]);
            if (EPI) {
                const float* bp = bias + (grow & 31) * 1024 + gcol;
                v.x = fmaxf(v.x + bp[0], 0.0f);
                v.y = fmaxf(v.y + bp[1], 0.0f);
                v.z = fmaxf(v.z + bp[2], 0.0f);
                v.w = fmaxf(v.w + bp[3], 0.0f);
            }
            *(float4*)&O[grow * 1024 + gcol] = v;
        }
    }
}

extern "C" void kernel_launch(void* const* d_in, const int* in_sizes, int n_in,
                              void* d_out, int out_size)
{
    const float* X     = (const float*)d_in[0];   // (256, 32768)
    const float* nodes = (const float*)d_in[1];   // (6, 32,32,32,32)
    const float* bias  = (const float*)d_in[2];   // (32768,)
    float* out = (float*)d_out;

    dim3 grid(NCOLS / BN, (BATCH * DLEG) / BM);   // (8, 64)
    dim3 block(256);

    // src/dst sel: 0 = external ptr, 1 = g_buf0, 2 = g_buf1
    entangler_gemm<0, false><<<grid, block>>>(X,       nodes + 0 * NODE_SZ, bias, nullptr, 0, 1);
    entangler_gemm<1, false><<<grid, block>>>(nullptr, nodes + 1 * NODE_SZ, bias, nullptr, 1, 2);
    entangler_gemm<1, false><<<grid, block>>>(nullptr, nodes + 2 * NODE_SZ, bias, nullptr, 2, 1);
    entangler_gemm<1, false><<<grid, block>>>(nullptr, nodes + 3 * NODE_SZ, bias, nullptr, 1, 2);
    entangler_gemm<1, false><<<grid, block>>>(nullptr, nodes + 4 * NODE_SZ, bias, nullptr, 2, 1);
    entangler_gemm<1, true ><<<grid, block>>>(nullptr, nodes + 5 * NODE_SZ, bias, out,     1, 0);
}

// round 6
// speedup vs baseline: 1.6270x; 1.6270x over previous
#include <cuda_runtime.h>
#include <cuda_bf16.h>
#include <cstdint>

// ---------------- problem constants ----------------
#define MROWS 8192          // B*D = 256*32
#define KDIM  1024
#define NCOLS 1024
#define NSTEPS 6

// ---------------- scratch (__device__ globals; no allocation) ----------------
__device__ __nv_bfloat16 g_ah[2][MROWS * KDIM];   // activation hi, ping/pong
__device__ __nv_bfloat16 g_al[2][MROWS * KDIM];   // activation lo
__device__ __nv_bfloat16 g_wh[NSTEPS][KDIM * NCOLS]; // Wt hi: [n][k]
__device__ __nv_bfloat16 g_wl[NSTEPS][KDIM * NCOLS]; // Wt lo

// ---------------- GEMM tiling ----------------
#define BM 128
#define BN 128
#define BK 32                 // 2 x k16 per stage
#define NKT (KDIM / BK)       // 32
#define NSTAGE 3

// smem: per stage: A[hl=2][ks=2][128 rows][24 bf16 (16 data + 8 pad)] then B same.
// row stride 48B -> ldmatrix conflict-free; block (hl,ks) = 128*48 = 6144 B.
#define ROW_B   48
#define BLK_B   (128 * ROW_B)     // 6144
#define AREG_B  (4 * BLK_B)       // 24576
#define STAGE_B (2 * AREG_B)      // 49152
#define SMEM_BYTES (NSTAGE * STAGE_B)   // 147456

__device__ __forceinline__ uint32_t s2u(const void* p) {
    uint32_t a;
    asm("{ .reg .u64 t; cvta.to.shared.u64 t, %1; cvt.u32.u64 %0, t; }" : "=r"(a) : "l"(p));
    return a;
}

__device__ __forceinline__ void ldm4(uint32_t* r, uint32_t a) {
    asm volatile("ldmatrix.sync.aligned.m8n8.x4.shared.b16 {%0,%1,%2,%3}, [%4];"
                 : "=r"(r[0]), "=r"(r[1]), "=r"(r[2]), "=r"(r[3]) : "r"(a));
}

__device__ __forceinline__ void mma_bf16(float* d, const uint32_t* a, const uint32_t* b) {
    asm volatile("mma.sync.aligned.m16n8k16.row.col.f32.bf16.bf16.f32 "
                 "{%0,%1,%2,%3}, {%4,%5,%6,%7}, {%8,%9}, {%0,%1,%2,%3};"
                 : "+f"(d[0]), "+f"(d[1]), "+f"(d[2]), "+f"(d[3])
                 : "r"(a[0]), "r"(a[1]), "r"(a[2]), "r"(a[3]), "r"(b[0]), "r"(b[1]));
}

__device__ __forceinline__ void split_bf16(float v, __nv_bfloat16& h, __nv_bfloat16& l) {
    h = __float2bfloat16(v);
    l = __float2bfloat16(v - __bfloat162float(h));
}

// ---------------- prep kernels ----------------

// A0[(b,f)][k=j*32+i] = X[b,i,j,f], split into hi/lo bf16.
__global__ void prep_x(const float* __restrict__ X) {
    __shared__ float t[32][33];
    const int b = blockIdx.x >> 5, j = blockIdx.x & 31;
    const int x = threadIdx.x, y = threadIdx.y;
    t[y][x] = X[b * 32768 + y * 1024 + j * 32 + x];   // y=i, x=f (coalesced)
    __syncthreads();
    const float v = t[x][y];                          // x=i, y=f
    __nv_bfloat16 h, l;
    split_bf16(v, h, l);
    const int addr = (b * 32 + y) * 1024 + j * 32 + x;  // row (b,f=y), col j*32+i
    g_ah[0][addr] = h;
    g_al[0][addr] = l;
}

// Wt[s][n][k] = W[s][(k&31)*32 + (k>>5)][n], split hi/lo.
__global__ void prep_w(const float* __restrict__ W) {
    __shared__ float t[32][33];
    const int s = blockIdx.z;
    const int k0 = blockIdx.x * 32, n0 = blockIdx.y * 32;
    const int x = threadIdx.x, y = threadIdx.y;
    const int kp = k0 + y;
    const int wrow = (kp & 31) * 32 + (kp >> 5);
    t[y][x] = W[s * 1048576 + wrow * 1024 + n0 + x];
    __syncthreads();
    const float v = t[x][y];
    __nv_bfloat16 h, l;
    split_bf16(v, h, l);
    const int addr = (n0 + y) * 1024 + k0 + x;
    g_wh[s][addr] = h;
    g_wl[s][addr] = l;
}

// ---------------- bf16x2 mma GEMM ----------------
// O[m][n] = sum_k A[m][k] * Wt[n][k]; A = Ahi+Alo, W = Whi+Wlo; compute hh+hl+lh.
template <bool EPI>
__global__ __launch_bounds__(256, 1)
void entangler_mma(int src, int dst, int s,
                   const float* __restrict__ bias, float* __restrict__ out) {
    extern __shared__ char smem[];
    const uint32_t smem_u = s2u(smem);

    const int tid  = threadIdx.x;
    const int wid  = tid >> 5;
    const int lane = tid & 31;
    const int col0 = blockIdx.x * BN;
    const int row0 = blockIdx.y * BM;
    const int warp_m = (wid & 3) * 32;
    const int warp_n = (wid >> 2) * 64;

    const __nv_bfloat16* __restrict__ Ahi = g_ah[src];
    const __nv_bfloat16* __restrict__ Alo = g_al[src];
    const __nv_bfloat16* __restrict__ Whi = g_wh[s];
    const __nv_bfloat16* __restrict__ Wlo = g_wl[s];
    __nv_bfloat16* __restrict__ Ahd = g_ah[dst];
    __nv_bfloat16* __restrict__ Ald = g_al[dst];

    float acc[2][8][4];
#pragma unroll
    for (int mt = 0; mt < 2; mt++)
#pragma unroll
        for (int nt = 0; nt < 8; nt++)
#pragma unroll
            for (int q = 0; q < 4; q++) acc[mt][nt][q] = 0.0f;

    // ---- cp.async staging: 8 x 16B chunks per thread per stage ----
    auto issue = [&](int kt, int stg) {
        const uint32_t sbase = smem_u + stg * STAGE_B;
#pragma unroll
        for (int t = 0; t < 4; t++) {
            const int idx  = tid + t * 256;          // 0..1023
            const int m_l  = idx >> 3;               // 0..127
            const int sub  = idx & 7;
            const int hl   = sub >> 2;               // 0=hi 1=lo
            const int ch   = sub & 3;                // 16B chunk within 64B k-range
            const int ks   = ch >> 1;
            const int half = ch & 1;
            const uint32_t soff = ((hl * 2 + ks) * 128 + m_l) * ROW_B + half * 16;

            const __nv_bfloat16* ga =
                (hl ? Alo : Ahi) + (row0 + m_l) * 1024 + kt * 32 + ch * 8;
            asm volatile("cp.async.cg.shared.global [%0], [%1], 16;"
                         :: "r"(sbase + soff), "l"(ga));
            const __nv_bfloat16* gb =
                (hl ? Wlo : Whi) + (col0 + m_l) * 1024 + kt * 32 + ch * 8;
            asm volatile("cp.async.cg.shared.global [%0], [%1], 16;"
                         :: "r"(sbase + AREG_B + soff), "l"(gb));
        }
        asm volatile("cp.async.commit_group;" ::: "memory");
    };

    // ---- fragment addresses (ldmatrix lane mapping) ----
    const int a_lr = (lane & 7) + ((lane >> 3) & 1) * 8;   // row within 16
    const int a_lb = (lane >> 4) * 16;                     // byte half
    const int b_nr = ((lane >> 4)) * 8 + (lane & 7);       // n-row within 16
    const int b_lb = ((lane >> 3) & 1) * 16;

    auto compute = [&](int stg) {
        const uint32_t sbase = smem_u + stg * STAGE_B;
#pragma unroll
        for (int ks = 0; ks < 2; ks++) {
            uint32_t ah[2][4], al[2][4], bh[8][2], bl[8][2];
#pragma unroll
            for (int mt = 0; mt < 2; mt++) {
                const uint32_t ra = (warp_m + mt * 16 + a_lr) * ROW_B + a_lb;
                ldm4(ah[mt], sbase + (0 + ks) * BLK_B + ra);
                ldm4(al[mt], sbase + (2 + ks) * BLK_B + ra);
            }
#pragma unroll
            for (int ntp = 0; ntp < 4; ntp++) {
                const uint32_t rb = (warp_n + ntp * 16 + b_nr) * ROW_B + b_lb;
                uint32_t tmp[4];
                ldm4(tmp, sbase + AREG_B + (0 + ks) * BLK_B + rb);
                bh[2 * ntp][0] = tmp[0]; bh[2 * ntp][1] = tmp[1];
                bh[2 * ntp + 1][0] = tmp[2]; bh[2 * ntp + 1][1] = tmp[3];
                ldm4(tmp, sbase + AREG_B + (2 + ks) * BLK_B + rb);
                bl[2 * ntp][0] = tmp[0]; bl[2 * ntp][1] = tmp[1];
                bl[2 * ntp + 1][0] = tmp[2]; bl[2 * ntp + 1][1] = tmp[3];
            }
#pragma unroll
            for (int mt = 0; mt < 2; mt++)
#pragma unroll
                for (int nt = 0; nt < 8; nt++) {
                    mma_bf16(acc[mt][nt], ah[mt], bh[nt]);   // hi*hi
                    mma_bf16(acc[mt][nt], ah[mt], bl[nt]);   // hi*lo
                    mma_bf16(acc[mt][nt], al[mt], bh[nt]);   // lo*hi
                }
        }
    };

    // ---- pipeline ----
    issue(0, 0);
    issue(1, 1);
#pragma unroll 1
    for (int kt = 0; kt < NKT; kt++) {
        asm volatile("cp.async.wait_group 1;" ::: "memory");
        __syncthreads();
        if (kt + 2 < NKT) issue(kt + 2, (kt + 2) % NSTAGE);
        else asm volatile("cp.async.commit_group;" ::: "memory");
        compute(kt % NSTAGE);
    }

    // ---- epilogue ----
    const int lrow = lane >> 2;
    const int lcol = (lane & 3) * 2;
#pragma unroll
    for (int mt = 0; mt < 2; mt++) {
#pragma unroll
        for (int nt = 0; nt < 8; nt++) {
            const int gr0 = row0 + warp_m + mt * 16 + lrow;
            const int gn  = col0 + warp_n + nt * 8 + lcol;
#pragma unroll
            for (int half = 0; half < 2; half++) {
                const int r = gr0 + half * 8;
                float v0 = acc[mt][nt][half * 2 + 0];
                float v1 = acc[mt][nt][half * 2 + 1];
                if (EPI) {
                    const int f = r & 31;
                    v0 = fmaxf(v0 + bias[f * 1024 + gn], 0.0f);
                    v1 = fmaxf(v1 + bias[f * 1024 + gn + 1], 0.0f);
                    float2 o = make_float2(v0, v1);
                    *(float2*)(out + r * 1024 + gn) = o;
                } else {
                    // scatter into next step's row-major A layout
                    const int b = r >> 5, f = r & 31;
                    const int addr = (b * 32 + (gn >> 5)) * 1024 + f * 32 + (gn & 31);
                    __nv_bfloat16 h0, l0, h1, l1;
                    split_bf16(v0, h0, l0);
                    split_bf16(v1, h1, l1);
                    __nv_bfloat162 hp; hp.x = h0; hp.y = h1;
                    __nv_bfloat162 lp; lp.x = l0; lp.y = l1;
                    *(__nv_bfloat162*)(&Ahd[addr]) = hp;
                    *(__nv_bfloat162*)(&Ald[addr]) = lp;
                }
            }
        }
    }
}

// ---------------- launch ----------------
extern "C" void kernel_launch(void* const* d_in, const int* in_sizes, int n_in,
                              void* d_out, int out_size) {
    const float* X     = (const float*)d_in[0];
    const float* nodes = (const float*)d_in[1];
    const float* bias  = (const float*)d_in[2];
    float* out = (float*)d_out;

    cudaFuncSetAttribute(entangler_mma<false>,
                         cudaFuncAttributeMaxDynamicSharedMemorySize, SMEM_BYTES);
    cudaFuncSetAttribute(entangler_mma<true>,
                         cudaFuncAttributeMaxDynamicSharedMemorySize, SMEM_BYTES);

    prep_x<<<MROWS, dim3(32, 32)>>>(X);
    prep_w<<<dim3(32, 32, NSTEPS), dim3(32, 32)>>>(nodes);

    dim3 grid(NCOLS / BN, MROWS / BM);   // (8, 64)
    entangler_mma<false><<<grid, 256, SMEM_BYTES>>>(0, 1, 0, bias, nullptr);
    entangler_mma<false><<<grid, 256, SMEM_BYTES>>>(1, 0, 1, bias, nullptr);
    entangler_mma<false><<<grid, 256, SMEM_BYTES>>>(0, 1, 2, bias, nullptr);
    entangler_mma<false><<<grid, 256, SMEM_BYTES>>>(1, 0, 3, bias, nullptr);
    entangler_mma<false><<<grid, 256, SMEM_BYTES>>>(0, 1, 4, bias, nullptr);
    entangler_mma<true ><<<grid, 256, SMEM_BYTES>>>(1, 0, 5, bias, out);
}

// round 7
// speedup vs baseline: 1.6348x; 1.0048x over previous
#include <cuda_runtime.h>
#include <cuda_bf16.h>
#include <cstdint>

// ---------------- problem constants ----------------
#define MROWS 8192          // B*D = 256*32
#define KDIM  1024
#define NCOLS 1024
#define NSTEPS 6

// ---------------- scratch (__device__ globals; no allocation) ----------------
__device__ __nv_bfloat16 g_ah[2][MROWS * KDIM];      // activation hi, ping/pong
__device__ __nv_bfloat16 g_al[2][MROWS * KDIM];      // activation lo
__device__ __nv_bfloat16 g_wh[NSTEPS][KDIM * NCOLS]; // Wt hi: [n][k]
__device__ __nv_bfloat16 g_wl[NSTEPS][KDIM * NCOLS]; // Wt lo

// ---------------- GEMM tiling ----------------
#define BM 128
#define BN 128
#define BK 32                 // 2 x k16 per stage
#define NKT (KDIM / BK)       // 32
#define NSTAGE 4
#define NTHREADS 512

// smem per stage: A[hl=2][ks=2][128 rows][16 bf16 + 8 pad] then B same.
#define ROW_B   48
#define BLK_B   (128 * ROW_B)     // 6144
#define AREG_B  (4 * BLK_B)       // 24576
#define STAGE_B (2 * AREG_B)      // 49152
#define SMEM_BYTES (NSTAGE * STAGE_B)   // 196608

__device__ __forceinline__ uint32_t s2u(const void* p) {
    uint32_t a;
    asm("{ .reg .u64 t; cvta.to.shared.u64 t, %1; cvt.u32.u64 %0, t; }" : "=r"(a) : "l"(p));
    return a;
}

__device__ __forceinline__ void ldm4(uint32_t* r, uint32_t a) {
    asm volatile("ldmatrix.sync.aligned.m8n8.x4.shared.b16 {%0,%1,%2,%3}, [%4];"
                 : "=r"(r[0]), "=r"(r[1]), "=r"(r[2]), "=r"(r[3]) : "r"(a));
}

__device__ __forceinline__ void mma_bf16(float* d, const uint32_t* a, const uint32_t* b) {
    asm volatile("mma.sync.aligned.m16n8k16.row.col.f32.bf16.bf16.f32 "
                 "{%0,%1,%2,%3}, {%4,%5,%6,%7}, {%8,%9}, {%0,%1,%2,%3};"
                 : "+f"(d[0]), "+f"(d[1]), "+f"(d[2]), "+f"(d[3])
                 : "r"(a[0]), "r"(a[1]), "r"(a[2]), "r"(a[3]), "r"(b[0]), "r"(b[1]));
}

__device__ __forceinline__ void split_bf16(float v, __nv_bfloat16& h, __nv_bfloat16& l) {
    h = __float2bfloat16(v);
    l = __float2bfloat16(v - __bfloat162float(h));
}

// ---------------- prep kernels ----------------

// A0[(b,f)][k=j*32+i] = X[b,i,j,f], split into hi/lo bf16.
__global__ void prep_x(const float* __restrict__ X) {
    __shared__ float t[32][33];
    const int b = blockIdx.x >> 5, j = blockIdx.x & 31;
    const int x = threadIdx.x, y = threadIdx.y;
    t[y][x] = X[b * 32768 + y * 1024 + j * 32 + x];   // y=i, x=f (coalesced)
    __syncthreads();
    const float v = t[x][y];                          // x=i, y=f
    __nv_bfloat16 h, l;
    split_bf16(v, h, l);
    const int addr = (b * 32 + y) * 1024 + j * 32 + x;  // row (b,f=y), col j*32+i
    g_ah[0][addr] = h;
    g_al[0][addr] = l;
}

// Wt[s][n][k] = W[s][(k&31)*32 + (k>>5)][n], split hi/lo.
__global__ void prep_w(const float* __restrict__ W) {
    __shared__ float t[32][33];
    const int s = blockIdx.z;
    const int k0 = blockIdx.x * 32, n0 = blockIdx.y * 32;
    const int x = threadIdx.x, y = threadIdx.y;
    const int kp = k0 + y;
    const int wrow = (kp & 31) * 32 + (kp >> 5);
    t[y][x] = W[s * 1048576 + wrow * 1024 + n0 + x];
    __syncthreads();
    const float v = t[x][y];
    __nv_bfloat16 h, l;
    split_bf16(v, h, l);
    const int addr = (n0 + y) * 1024 + k0 + x;
    g_wh[s][addr] = h;
    g_wl[s][addr] = l;
}

// ---------------- bf16x2 mma GEMM ----------------
// O[m][n] = sum_k A[m][k] * Wt[n][k]; A = Ahi+Alo, W = Whi+Wlo; compute hh+hl+lh.
// 512 threads: 16 warps in 4x4 layout, warp tile 32x32.
template <bool EPI>
__global__ __launch_bounds__(NTHREADS, 1)
void entangler_mma(int src, int dst, int s,
                   const float* __restrict__ bias, float* __restrict__ out) {
    extern __shared__ char smem[];
    const uint32_t smem_u = s2u(smem);

    const int tid  = threadIdx.x;
    const int wid  = tid >> 5;
    const int lane = tid & 31;
    const int col0 = blockIdx.x * BN;
    const int row0 = blockIdx.y * BM;
    const int warp_m = (wid & 3) * 32;
    const int warp_n = (wid >> 2) * 32;

    const __nv_bfloat16* __restrict__ Ahi = g_ah[src];
    const __nv_bfloat16* __restrict__ Alo = g_al[src];
    const __nv_bfloat16* __restrict__ Whi = g_wh[s];
    const __nv_bfloat16* __restrict__ Wlo = g_wl[s];
    __nv_bfloat16* __restrict__ Ahd = g_ah[dst];
    __nv_bfloat16* __restrict__ Ald = g_al[dst];

    float acc[2][4][4];
#pragma unroll
    for (int mt = 0; mt < 2; mt++)
#pragma unroll
        for (int nt = 0; nt < 4; nt++)
#pragma unroll
            for (int q = 0; q < 4; q++) acc[mt][nt][q] = 0.0f;

    // ---- cp.async staging: each idx handles one A chunk + one B chunk (16B) ----
    auto issue = [&](int kt, int stg) {
        const uint32_t sbase = smem_u + stg * STAGE_B;
#pragma unroll
        for (int t = 0; t < 2; t++) {
            const int idx  = tid + t * NTHREADS;     // 0..1023
            const int m_l  = idx >> 3;               // 0..127
            const int sub  = idx & 7;
            const int hl   = sub >> 2;               // 0=hi 1=lo
            const int ch   = sub & 3;                // 16B chunk within 64B k-range
            const int ks   = ch >> 1;
            const int half = ch & 1;
            const uint32_t soff = ((hl * 2 + ks) * 128 + m_l) * ROW_B + half * 16;

            const __nv_bfloat16* ga =
                (hl ? Alo : Ahi) + (row0 + m_l) * 1024 + kt * 32 + ch * 8;
            asm volatile("cp.async.cg.shared.global [%0], [%1], 16;"
                         :: "r"(sbase + soff), "l"(ga));
            const __nv_bfloat16* gb =
                (hl ? Wlo : Whi) + (col0 + m_l) * 1024 + kt * 32 + ch * 8;
            asm volatile("cp.async.cg.shared.global [%0], [%1], 16;"
                         :: "r"(sbase + AREG_B + soff), "l"(gb));
        }
        asm volatile("cp.async.commit_group;" ::: "memory");
    };

    // ---- ldmatrix lane mappings (validated in round 6) ----
    const int a_lr = (lane & 7) + ((lane >> 3) & 1) * 8;
    const int a_lb = (lane >> 4) * 16;
    const int b_nr = (lane >> 4) * 8 + (lane & 7);
    const int b_lb = ((lane >> 3) & 1) * 16;

    auto compute = [&](int stg) {
        const uint32_t sbase = smem_u + stg * STAGE_B;
#pragma unroll
        for (int ks = 0; ks < 2; ks++) {
            uint32_t ah[2][4], al[2][4], bh[4][2], bl[4][2];
#pragma unroll
            for (int mt = 0; mt < 2; mt++) {
                const uint32_t ra = (warp_m + mt * 16 + a_lr) * ROW_B + a_lb;
                ldm4(ah[mt], sbase + (0 + ks) * BLK_B + ra);
                ldm4(al[mt], sbase + (2 + ks) * BLK_B + ra);
            }
#pragma unroll
            for (int ntp = 0; ntp < 2; ntp++) {
                const uint32_t rb = (warp_n + ntp * 16 + b_nr) * ROW_B + b_lb;
                uint32_t tmp[4];
                ldm4(tmp, sbase + AREG_B + (0 + ks) * BLK_B + rb);
                bh[2 * ntp][0] = tmp[0]; bh[2 * ntp][1] = tmp[1];
                bh[2 * ntp + 1][0] = tmp[2]; bh[2 * ntp + 1][1] = tmp[3];
                ldm4(tmp, sbase + AREG_B + (2 + ks) * BLK_B + rb);
                bl[2 * ntp][0] = tmp[0]; bl[2 * ntp][1] = tmp[1];
                bl[2 * ntp + 1][0] = tmp[2]; bl[2 * ntp + 1][1] = tmp[3];
            }
            // three passes: dependency distance 8 between same-acc MMAs
#pragma unroll
            for (int mt = 0; mt < 2; mt++)
#pragma unroll
                for (int nt = 0; nt < 4; nt++)
                    mma_bf16(acc[mt][nt], ah[mt], bh[nt]);   // hi*hi
#pragma unroll
            for (int mt = 0; mt < 2; mt++)
#pragma unroll
                for (int nt = 0; nt < 4; nt++)
                    mma_bf16(acc[mt][nt], ah[mt], bl[nt]);   // hi*lo
#pragma unroll
            for (int mt = 0; mt < 2; mt++)
#pragma unroll
                for (int nt = 0; nt < 4; nt++)
                    mma_bf16(acc[mt][nt], al[mt], bh[nt]);   // lo*hi
        }
    };

    // ---- 4-stage pipeline ----
    issue(0, 0);
    issue(1, 1);
    issue(2, 2);
#pragma unroll 1
    for (int kt = 0; kt < NKT; kt++) {
        asm volatile("cp.async.wait_group 2;" ::: "memory");
        __syncthreads();
        if (kt + 3 < NKT) issue(kt + 3, (kt + 3) & 3);
        else asm volatile("cp.async.commit_group;" ::: "memory");
        compute(kt & 3);
    }

    // ---- epilogue ----
    const int lrow = lane >> 2;
    const int lcol = (lane & 3) * 2;
#pragma unroll
    for (int mt = 0; mt < 2; mt++) {
#pragma unroll
        for (int nt = 0; nt < 4; nt++) {
            const int gr0 = row0 + warp_m + mt * 16 + lrow;
            const int gn  = col0 + warp_n + nt * 8 + lcol;
#pragma unroll
            for (int half = 0; half < 2; half++) {
                const int r = gr0 + half * 8;
                float v0 = acc[mt][nt][half * 2 + 0];
                float v1 = acc[mt][nt][half * 2 + 1];
                if (EPI) {
                    const int f = r & 31;
                    v0 = fmaxf(v0 + bias[f * 1024 + gn], 0.0f);
                    v1 = fmaxf(v1 + bias[f * 1024 + gn + 1], 0.0f);
                    float2 o = make_float2(v0, v1);
                    *(float2*)(out + r * 1024 + gn) = o;
                } else {
                    // scatter into next step's row-major A layout
                    const int b = r >> 5, f = r & 31;
                    const int addr = (b * 32 + (gn >> 5)) * 1024 + f * 32 + (gn & 31);
                    __nv_bfloat16 h0, l0, h1, l1;
                    split_bf16(v0, h0, l0);
                    split_bf16(v1, h1, l1);
                    __nv_bfloat162 hp; hp.x = h0; hp.y = h1;
                    __nv_bfloat162 lp; lp.x = l0; lp.y = l1;
                    *(__nv_bfloat162*)(&Ahd[addr]) = hp;
                    *(__nv_bfloat162*)(&Ald[addr]) = lp;
                }
            }
        }
    }
}

// ---------------- launch ----------------
extern "C" void kernel_launch(void* const* d_in, const int* in_sizes, int n_in,
                              void* d_out, int out_size) {
    const float* X     = (const float*)d_in[0];
    const float* nodes = (const float*)d_in[1];
    const float* bias  = (const float*)d_in[2];
    float* out = (float*)d_out;

    cudaFuncSetAttribute(entangler_mma<false>,
                         cudaFuncAttributeMaxDynamicSharedMemorySize, SMEM_BYTES);
    cudaFuncSetAttribute(entangler_mma<true>,
                         cudaFuncAttributeMaxDynamicSharedMemorySize, SMEM_BYTES);

    prep_x<<<MROWS, dim3(32, 32)>>>(X);
    prep_w<<<dim3(32, 32, NSTEPS), dim3(32, 32)>>>(nodes);

    dim3 grid(NCOLS / BN, MROWS / BM);   // (8, 64)
    entangler_mma<false><<<grid, NTHREADS, SMEM_BYTES>>>(0, 1, 0, bias, nullptr);
    entangler_mma<false><<<grid, NTHREADS, SMEM_BYTES>>>(1, 0, 1, bias, nullptr);
    entangler_mma<false><<<grid, NTHREADS, SMEM_BYTES>>>(0, 1, 2, bias, nullptr);
    entangler_mma<false><<<grid, NTHREADS, SMEM_BYTES>>>(1, 0, 3, bias, nullptr);
    entangler_mma<false><<<grid, NTHREADS, SMEM_BYTES>>>(0, 1, 4, bias, nullptr);
    entangler_mma<true ><<<grid, NTHREADS, SMEM_BYTES>>>(1, 0, 5, bias, out);
}